// round 10
// baseline (speedup 1.0000x reference)
#include <cuda_runtime.h>

#define DX 256
#define DY 256
#define DZ 32
#define VOL (DX * DY * DZ)   // 2,097,152

// Precomputed int16 weights, interleaved [dir][voxel][8] (16B/voxel) = 96 MB,
// plus 8 MB ping-pong scratch. Device globals = the allowed scratch mechanism.
__device__ uint4 g_weights[3][VOL];
__device__ float g_scratch[VOL];

// Neighbor shift tables (row, col) from the reference ZeroPad2d set.
// DIR=0: row->x, col->y (channels 0..7);  DIR=1: row->x, col->z (8..15);
// DIR=2: row->y, col->z (16..23).
__device__ __constant__ const int c_dr[8] = { 1, 1, 1, 0, 0, -1, -1, -1 };
__device__ __constant__ const int c_dc[8] = { 1, 0, -1, 1, -1, 1, 0, -1 };

// Single-use guidance: stream through, evict first.
__device__ __forceinline__ float ldcs(const float* p) {
    float v;
    asm volatile("ld.global.cs.f32 %0, [%1];" : "=f"(v) : "l"(p));
    return v;
}
// 256-bit accesses with L2 evict-last (the only width ptxas allows it on).
__device__ __forceinline__ void ldg256_sticky(const uint4* p, uint4& a, uint4& b) {
    asm volatile("ld.global.L2::evict_last.v8.b32 {%0,%1,%2,%3,%4,%5,%6,%7}, [%8];"
                 : "=r"(a.x), "=r"(a.y), "=r"(a.z), "=r"(a.w),
                   "=r"(b.x), "=r"(b.y), "=r"(b.z), "=r"(b.w)
                 : "l"(p));
}
__device__ __forceinline__ void stg256_sticky(uint4* p, uint4 a, uint4 b) {
    asm volatile("st.global.L2::evict_last.v8.b32 [%0], {%1,%2,%3,%4,%5,%6,%7,%8};"
                 :: "l"(p),
                    "r"(a.x), "r"(a.y), "r"(a.z), "r"(a.w),
                    "r"(b.x), "r"(b.y), "r"(b.z), "r"(b.w)
                 : "memory");
}
// Fire-and-forget L2 prefetch (no destination register, no scoreboard).
__device__ __forceinline__ void prefetchL2(const void* p) {
    asm volatile("prefetch.global.L2 [%0];" :: "l"(p));
}

// ---------------------------------------------------------------------------
// Pass 1: gather 8 guidance values at neighbor positions, abs-sum normalize,
// quantize to int16 (x32767). Two adjacent voxels per thread -> one 256-bit
// sticky store. Optionally prefetches the slab the FIRST prop step will use
// (it was evicted by the guidance stream after being written).
// ---------------------------------------------------------------------------
template <int DIR>
__global__ __launch_bounds__(256) void make_weights(
    const float* __restrict__ G, uint4* __restrict__ W,
    const uint4* __restrict__ Wpf)
{
    const int t = (blockIdx.x * 256 + threadIdx.x) * 2;
    const int z0 = t & 31, y = (t >> 5) & 255, x = t >> 13;

    if (Wpf && ((threadIdx.x & 3) == 0)) prefetchL2(Wpf + t);  // 128B line / 4 threads

    uint4 wp[2];
#pragma unroll
    for (int v = 0; v < 2; ++v) {
        const int z = z0 + v;
        float g[8];
        float asum = 0.f;
#pragma unroll
        for (int k = 0; k < 8; ++k) {
            const int dr = c_dr[k], dc = c_dc[k];
            int nx, ny, nz; bool ok;
            if (DIR == 0)      { nx = x + dr; ny = y + dc; nz = z;
                                 ok = ((unsigned)nx < DX) & ((unsigned)ny < DY); }
            else if (DIR == 1) { nx = x + dr; ny = y;      nz = z + dc;
                                 ok = ((unsigned)nx < DX) & ((unsigned)nz < DZ); }
            else               { nx = x;      ny = y + dr; nz = z + dc;
                                 ok = ((unsigned)ny < DY) & ((unsigned)nz < DZ); }
            float gv = 0.f;
            if (ok) gv = ldcs(&G[(DIR * 8 + k) * VOL + (nx * DY + ny) * DZ + nz]);
            g[k] = gv;
            asum += fabsf(gv);
        }

        const float s = 32767.f / asum;
        int q[8];
#pragma unroll
        for (int k = 0; k < 8; ++k) q[k] = __float2int_rn(g[k] * s);

        wp[v].x = (q[0] & 0xffff) | (q[1] << 16);
        wp[v].y = (q[2] & 0xffff) | (q[3] << 16);
        wp[v].z = (q[4] & 0xffff) | (q[5] << 16);
        wp[v].w = (q[6] & 0xffff) | (q[7] << 16);
    }
    stg256_sticky(&W[t], wp[0], wp[1]);
}

// ---------------------------------------------------------------------------
// Pass 2 (x9): two adjacent voxels per thread (R8 config: 32 regs, occ ~76%).
// Additionally prefetches the NEXT step's weight slab into L2 using the
// ~50% spare DRAM bandwidth, so the next kernel's weight reads are L2 hits.
// out = bc + (sum_k w_k*b_k - (sum_k w_k)*bc) / 32767.
// Invalid neighbors have w_k == 0; address is clamped to center (value unused).
// ---------------------------------------------------------------------------
template <int DIR>
__global__ __launch_bounds__(256) void prop_step(
    const uint4* __restrict__ W,
    const uint4* __restrict__ Wnext,
    const float* __restrict__ S,
    float* __restrict__ D)
{
    const int t = (blockIdx.x * 256 + threadIdx.x) * 2;
    const int z = t & 31, y = (t >> 5) & 255, x = t >> 13;

    if (Wnext && ((threadIdx.x & 3) == 0)) prefetchL2(Wnext + t);  // one line / 4 thr

    uint4 w0, w1;
    ldg256_sticky(&W[t], w0, w1);
    const float2 bc = *reinterpret_cast<const float2*>(S + t);

    float b0[8], b1[8];
    if (DIR == 0) {
        // Shifts in (x,y) only: both voxels share delta; float2 loads stay aligned.
#pragma unroll
        for (int k = 0; k < 8; ++k) {
            const int dr = c_dr[k], dc = c_dc[k];
            const bool ok = ((unsigned)(x + dr) < DX) & ((unsigned)(y + dc) < DY);
            const int delta = dr * (DY * DZ) + dc * DZ;
            const float2 bb = *reinterpret_cast<const float2*>(S + (ok ? t + delta : t));
            b0[k] = bb.x; b1[k] = bb.y;
        }
    } else {
#pragma unroll
        for (int k = 0; k < 8; ++k) {
            const int dr = c_dr[k], dc = c_dc[k];
            const int  row = (DIR == 1) ? dr * (DY * DZ) : dr * DZ;
            const bool rok = (DIR == 1) ? ((unsigned)(x + dr) < DX)
                                        : ((unsigned)(y + dr) < DY);
            const bool ok0 = rok & ((unsigned)(z + dc)     < DZ);
            const bool ok1 = rok & ((unsigned)(z + 1 + dc) < DZ);
            b0[k] = __ldg(&S[ok0 ? t + row + dc     : t]);
            b1[k] = __ldg(&S[ok1 ? t + 1 + row + dc : t]);
        }
    }

    float2 r;
    {
        float wf[8];
        wf[0] = (float)(short)(w0.x & 0xffff); wf[1] = (float)(short)(w0.x >> 16);
        wf[2] = (float)(short)(w0.y & 0xffff); wf[3] = (float)(short)(w0.y >> 16);
        wf[4] = (float)(short)(w0.z & 0xffff); wf[5] = (float)(short)(w0.z >> 16);
        wf[6] = (float)(short)(w0.w & 0xffff); wf[7] = (float)(short)(w0.w >> 16);
        float acc = 0.f, gs = 0.f;
#pragma unroll
        for (int k = 0; k < 8; ++k) { acc = fmaf(wf[k], b0[k], acc); gs += wf[k]; }
        r.x = fmaf(fmaf(-gs, bc.x, acc), 1.f / 32767.f, bc.x);
    }
    {
        float wf[8];
        wf[0] = (float)(short)(w1.x & 0xffff); wf[1] = (float)(short)(w1.x >> 16);
        wf[2] = (float)(short)(w1.y & 0xffff); wf[3] = (float)(short)(w1.y >> 16);
        wf[4] = (float)(short)(w1.z & 0xffff); wf[5] = (float)(short)(w1.z >> 16);
        wf[6] = (float)(short)(w1.w & 0xffff); wf[7] = (float)(short)(w1.w >> 16);
        float acc = 0.f, gs = 0.f;
#pragma unroll
        for (int k = 0; k < 8; ++k) { acc = fmaf(wf[k], b1[k], acc); gs += wf[k]; }
        r.y = fmaf(fmaf(-gs, bc.y, acc), 1.f / 32767.f, bc.y);
    }
    *reinterpret_cast<float2*>(D + t) = r;
}

extern "C" void kernel_launch(void* const* d_in, const int* in_sizes, int n_in,
                              void* d_out, int out_size)
{
    const float* G    = (const float*)d_in[0];  // guidance [24,256,256,32]
    const float* blur = (const float*)d_in[1];  // blur [1,256,256,32]
    float* out = (float*)d_out;

    void* wp = nullptr;  cudaGetSymbolAddress(&wp, g_weights);
    void* sp = nullptr;  cudaGetSymbolAddress(&sp, g_scratch);
    uint4* W   = (uint4*)wp;
    float* scr = (float*)sp;

    const int grid = (VOL / 2) / 256;   // 4096 blocks, 2 voxels/thread

    // Pass 1: build weights (guidance read exactly once). The dir-2 kernel
    // prefetches slab 0 back into L2 for the first prop step.
    make_weights<0><<<grid, 256>>>(G, W + 0 * VOL, nullptr);
    make_weights<1><<<grid, 256>>>(G, W + 1 * VOL, nullptr);
    make_weights<2><<<grid, 256>>>(G, W + 2 * VOL, W + 0 * VOL);

    // Pass 2: 9 propagation steps (dir 0,1,2 x 3); each step prefetches the
    // next step's slab. Ping-pong so the 9th write lands in d_out.
    const float* src = blur;
    float* bufs[2] = { out, scr };
    int wsel = 0;

    for (int it = 0; it < 3; ++it) {
        const bool last = (it == 2);
        prop_step<0><<<grid, 256>>>(W + 0 * VOL, W + 1 * VOL, src, bufs[wsel]);
        src = bufs[wsel]; wsel ^= 1;
        prop_step<1><<<grid, 256>>>(W + 1 * VOL, W + 2 * VOL, src, bufs[wsel]);
        src = bufs[wsel]; wsel ^= 1;
        prop_step<2><<<grid, 256>>>(W + 2 * VOL, last ? nullptr : W + 0 * VOL,
                                    src, bufs[wsel]);
        src = bufs[wsel]; wsel ^= 1;
    }
}

// round 12
// speedup vs baseline: 1.0167x; 1.0167x over previous
#include <cuda_runtime.h>

#define DX 256
#define DY 256
#define DZ 32
#define VOL (DX * DY * DZ)   // 2,097,152

// Precomputed int16 weights, interleaved [dir][voxel][8] (16B/voxel) = 96 MB,
// plus 8 MB ping-pong scratch. Device globals = the allowed scratch mechanism.
__device__ uint4 g_weights[3][VOL];
__device__ float g_scratch[VOL];

// Neighbor shift tables (row, col) from the reference ZeroPad2d set.
// DIR=0: row->x, col->y (channels 0..7);  DIR=1: row->x, col->z (8..15);
// DIR=2: row->y, col->z (16..23).
__device__ __constant__ const int c_dr[8] = { 1, 1, 1, 0, 0, -1, -1, -1 };
__device__ __constant__ const int c_dc[8] = { 1, 0, -1, 1, -1, 1, 0, -1 };

// Single-use guidance: stream through, evict first.
__device__ __forceinline__ float ldcs(const float* p) {
    float v;
    asm volatile("ld.global.cs.f32 %0, [%1];" : "=f"(v) : "l"(p));
    return v;
}
// 256-bit accesses with L2 evict-last (the only width ptxas allows it on).
__device__ __forceinline__ void ldg256_sticky(const uint4* p, uint4& a, uint4& b) {
    asm volatile("ld.global.L2::evict_last.v8.b32 {%0,%1,%2,%3,%4,%5,%6,%7}, [%8];"
                 : "=r"(a.x), "=r"(a.y), "=r"(a.z), "=r"(a.w),
                   "=r"(b.x), "=r"(b.y), "=r"(b.z), "=r"(b.w)
                 : "l"(p));
}
__device__ __forceinline__ void stg256_sticky(uint4* p, uint4 a, uint4 b) {
    asm volatile("st.global.L2::evict_last.v8.b32 [%0], {%1,%2,%3,%4,%5,%6,%7,%8};"
                 :: "l"(p),
                    "r"(a.x), "r"(a.y), "r"(a.z), "r"(a.w),
                    "r"(b.x), "r"(b.y), "r"(b.z), "r"(b.w)
                 : "memory");
}
// Fire-and-forget L2 prefetch (no destination register, no scoreboard).
__device__ __forceinline__ void prefetchL2(const void* p) {
    asm volatile("prefetch.global.L2 [%0];" :: "l"(p));
}

// ---------------------------------------------------------------------------
// Pass 1: gather 8 guidance values at neighbor positions, abs-sum normalize,
// quantize to int16 (x32767). Two adjacent voxels per thread -> one 256-bit
// sticky store. Optionally prefetches (AT THE END, after its own work) the
// slab the first prop step will use.
// ---------------------------------------------------------------------------
template <int DIR>
__global__ __launch_bounds__(256) void make_weights(
    const float* __restrict__ G, uint4* __restrict__ W,
    const uint4* __restrict__ Wpf)
{
    const int t = (blockIdx.x * 256 + threadIdx.x) * 2;
    const int z0 = t & 31, y = (t >> 5) & 255, x = t >> 13;

    uint4 wp[2];
#pragma unroll
    for (int v = 0; v < 2; ++v) {
        const int z = z0 + v;
        float g[8];
        float asum = 0.f;
#pragma unroll
        for (int k = 0; k < 8; ++k) {
            const int dr = c_dr[k], dc = c_dc[k];
            int nx, ny, nz; bool ok;
            if (DIR == 0)      { nx = x + dr; ny = y + dc; nz = z;
                                 ok = ((unsigned)nx < DX) & ((unsigned)ny < DY); }
            else if (DIR == 1) { nx = x + dr; ny = y;      nz = z + dc;
                                 ok = ((unsigned)nx < DX) & ((unsigned)nz < DZ); }
            else               { nx = x;      ny = y + dr; nz = z + dc;
                                 ok = ((unsigned)ny < DY) & ((unsigned)nz < DZ); }
            float gv = 0.f;
            if (ok) gv = ldcs(&G[(DIR * 8 + k) * VOL + (nx * DY + ny) * DZ + nz]);
            g[k] = gv;
            asum += fabsf(gv);
        }

        const float s = 32767.f / asum;
        int q[8];
#pragma unroll
        for (int k = 0; k < 8; ++k) q[k] = __float2int_rn(g[k] * s);

        wp[v].x = (q[0] & 0xffff) | (q[1] << 16);
        wp[v].y = (q[2] & 0xffff) | (q[3] << 16);
        wp[v].z = (q[4] & 0xffff) | (q[5] << 16);
        wp[v].w = (q[6] & 0xffff) | (q[7] << 16);
    }
    stg256_sticky(&W[t], wp[0], wp[1]);

    // Tail prefetch: data-dependent predicate (always true) pins it after the work.
    if (Wpf && ((threadIdx.x & 3) == 0) && (wp[1].w != 0x80000000u))
        prefetchL2(Wpf + t);
}

// ---------------------------------------------------------------------------
// Pass 2 (x9): two adjacent voxels per thread.
//   weights: 1 x LDG.256 sticky.
//   DIR0: center float2 + 8 aligned float2 neighbors.
//   DIR1/2: 3 rows x (aligned float2 + 2 edge scalars); center = row[1].
//   1 float2 store. Tail-prefetch of next step's weight slab.
// out = bc + (sum_k w_k*b_k - (sum_k w_k)*bc) / 32767.
// Invalid neighbors have w_k == 0; addresses are clamped (value unused).
// ---------------------------------------------------------------------------
template <int DIR>
__global__ __launch_bounds__(256) void prop_step(
    const uint4* __restrict__ W,
    const uint4* __restrict__ Wnext,
    const float* __restrict__ S,
    float* __restrict__ D)
{
    const int t = (blockIdx.x * 256 + threadIdx.x) * 2;
    const int z = t & 31, y = (t >> 5) & 255, x = t >> 13;

    uint4 w0, w1;
    ldg256_sticky(&W[t], w0, w1);

    float2 bc;
    float b0[8], b1[8];

    if (DIR == 0) {
        bc = *reinterpret_cast<const float2*>(S + t);
        // Shifts in (x,y) only: both voxels share delta; float2 loads stay aligned.
#pragma unroll
        for (int k = 0; k < 8; ++k) {
            const int dr = c_dr[k], dc = c_dc[k];
            const bool ok = ((unsigned)(x + dr) < DX) & ((unsigned)(y + dc) < DY);
            const int delta = dr * (DY * DZ) + dc * DZ;
            const float2 bb = *reinterpret_cast<const float2*>(S + (ok ? t + delta : t));
            b0[k] = bb.x; b1[k] = bb.y;
        }
    } else {
        // Rows -1,0,+1 along x (DIR1) or y (DIR2); z-shifts built in registers.
        float2 q[3]; float em[3], ep[3];
#pragma unroll
        for (int r = 0; r < 3; ++r) {
            const int d   = r - 1;
            const int row = (DIR == 1) ? d * (DY * DZ) : d * DZ;
            const bool rok = (DIR == 1) ? ((unsigned)(x + d) < DX)
                                        : ((unsigned)(y + d) < DY);
            const float* base = S + (rok ? t + row : t);
            q[r]  = *reinterpret_cast<const float2*>(base);
            em[r] = __ldg(base - (z > 0  ? 1 : 0));   // z-1  (clamped at z==0)
            ep[r] = __ldg(base + (z < 30 ? 2 : 0));   // z+2  (clamped at z==30)
        }
        bc = q[1];
#pragma unroll
        for (int k = 0; k < 8; ++k) {
            const int r = c_dr[k] + 1, dc = c_dc[k];
            if (dc == 0)      { b0[k] = q[r].x; b1[k] = q[r].y; }
            else if (dc == 1) { b0[k] = q[r].y; b1[k] = ep[r];  }
            else              { b0[k] = em[r];  b1[k] = q[r].x; }
        }
    }

    float2 r2;
    {
        float wf[8];
        wf[0] = (float)(short)(w0.x & 0xffff); wf[1] = (float)(short)(w0.x >> 16);
        wf[2] = (float)(short)(w0.y & 0xffff); wf[3] = (float)(short)(w0.y >> 16);
        wf[4] = (float)(short)(w0.z & 0xffff); wf[5] = (float)(short)(w0.z >> 16);
        wf[6] = (float)(short)(w0.w & 0xffff); wf[7] = (float)(short)(w0.w >> 16);
        float acc = 0.f, gs = 0.f;
#pragma unroll
        for (int k = 0; k < 8; ++k) { acc = fmaf(wf[k], b0[k], acc); gs += wf[k]; }
        r2.x = fmaf(fmaf(-gs, bc.x, acc), 1.f / 32767.f, bc.x);
    }
    {
        float wf[8];
        wf[0] = (float)(short)(w1.x & 0xffff); wf[1] = (float)(short)(w1.x >> 16);
        wf[2] = (float)(short)(w1.y & 0xffff); wf[3] = (float)(short)(w1.y >> 16);
        wf[4] = (float)(short)(w1.z & 0xffff); wf[5] = (float)(short)(w1.z >> 16);
        wf[6] = (float)(short)(w1.w & 0xffff); wf[7] = (float)(short)(w1.w >> 16);
        float acc = 0.f, gs = 0.f;
#pragma unroll
        for (int k = 0; k < 8; ++k) { acc = fmaf(wf[k], b1[k], acc); gs += wf[k]; }
        r2.y = fmaf(fmaf(-gs, bc.y, acc), 1.f / 32767.f, bc.y);
    }

    // Tail prefetch of next slab: predicate depends on r2 (never-true NaN
    // pattern check) so it cannot be hoisted above the loads/compute.
    if (Wnext && ((threadIdx.x & 3) == 0) && (__float_as_int(r2.x) != 0x7f800001))
        prefetchL2(Wnext + t);

    *reinterpret_cast<float2*>(D + t) = r2;
}

extern "C" void kernel_launch(void* const* d_in, const int* in_sizes, int n_in,
                              void* d_out, int out_size)
{
    const float* G    = (const float*)d_in[0];  // guidance [24,256,256,32]
    const float* blur = (const float*)d_in[1];  // blur [1,256,256,32]
    float* out = (float*)d_out;

    void* wp = nullptr;  cudaGetSymbolAddress(&wp, g_weights);
    void* sp = nullptr;  cudaGetSymbolAddress(&sp, g_scratch);
    uint4* W   = (uint4*)wp;
    float* scr = (float*)sp;

    const int grid = (VOL / 2) / 256;   // 4096 blocks, 2 voxels/thread

    // Pass 1: build weights (guidance read exactly once). The dir-2 kernel
    // tail-prefetches slab 0 back into L2 for the first prop step.
    make_weights<0><<<grid, 256>>>(G, W + 0 * VOL, nullptr);
    make_weights<1><<<grid, 256>>>(G, W + 1 * VOL, nullptr);
    make_weights<2><<<grid, 256>>>(G, W + 2 * VOL, W + 0 * VOL);

    // Pass 2: 9 propagation steps (dir 0,1,2 x 3); each step tail-prefetches
    // the next step's slab. Ping-pong so the 9th write lands in d_out.
    const float* src = blur;
    float* bufs[2] = { out, scr };
    int wsel = 0;

    for (int it = 0; it < 3; ++it) {
        const bool last = (it == 2);
        prop_step<0><<<grid, 256>>>(W + 0 * VOL, W + 1 * VOL, src, bufs[wsel]);
        src = bufs[wsel]; wsel ^= 1;
        prop_step<1><<<grid, 256>>>(W + 1 * VOL, W + 2 * VOL, src, bufs[wsel]);
        src = bufs[wsel]; wsel ^= 1;
        prop_step<2><<<grid, 256>>>(W + 2 * VOL, last ? nullptr : W + 0 * VOL,
                                    src, bufs[wsel]);
        src = bufs[wsel]; wsel ^= 1;
    }
}

// round 13
// speedup vs baseline: 1.2052x; 1.1854x over previous
#include <cuda_runtime.h>

#define DX 256
#define DY 256
#define DZ 32
#define VOL (DX * DY * DZ)   // 2,097,152

// Precomputed int16 weights, interleaved [dir][voxel][8] (16B/voxel) = 96 MB,
// plus 8 MB ping-pong scratch. Device globals = the allowed scratch mechanism.
__device__ uint4 g_weights[3][VOL];
__device__ float g_scratch[VOL];

// Neighbor shift tables (row, col) from the reference ZeroPad2d set.
// DIR=0: row->x, col->y (channels 0..7);  DIR=1: row->x, col->z (8..15);
// DIR=2: row->y, col->z (16..23).
__device__ __constant__ const int c_dr[8] = { 1, 1, 1, 0, 0, -1, -1, -1 };
__device__ __constant__ const int c_dc[8] = { 1, 0, -1, 1, -1, 1, 0, -1 };

// Single-use guidance: stream through, evict first.
__device__ __forceinline__ float ldcs(const float* p) {
    float v;
    asm volatile("ld.global.cs.f32 %0, [%1];" : "=f"(v) : "l"(p));
    return v;
}
// 256-bit accesses with L2 evict-last (the only width ptxas allows it on).
__device__ __forceinline__ void ldg256_sticky(const uint4* p, uint4& a, uint4& b) {
    asm volatile("ld.global.L2::evict_last.v8.b32 {%0,%1,%2,%3,%4,%5,%6,%7}, [%8];"
                 : "=r"(a.x), "=r"(a.y), "=r"(a.z), "=r"(a.w),
                   "=r"(b.x), "=r"(b.y), "=r"(b.z), "=r"(b.w)
                 : "l"(p));
}
__device__ __forceinline__ void stg256_sticky(uint4* p, uint4 a, uint4 b) {
    asm volatile("st.global.L2::evict_last.v8.b32 [%0], {%1,%2,%3,%4,%5,%6,%7,%8};"
                 :: "l"(p),
                    "r"(a.x), "r"(a.y), "r"(a.z), "r"(a.w),
                    "r"(b.x), "r"(b.y), "r"(b.z), "r"(b.w)
                 : "memory");
}

__device__ __forceinline__ void decode8(const uint4 w, float* wf) {
    wf[0] = (float)(short)(w.x & 0xffff); wf[1] = (float)(short)(w.x >> 16);
    wf[2] = (float)(short)(w.y & 0xffff); wf[3] = (float)(short)(w.y >> 16);
    wf[4] = (float)(short)(w.z & 0xffff); wf[5] = (float)(short)(w.z >> 16);
    wf[6] = (float)(short)(w.w & 0xffff); wf[7] = (float)(short)(w.w >> 16);
}

// Shared blur-neighbor gather for a 2-voxel pair (t even). b0/b1 per k.
// Invalid neighbors are clamped in address; their weights are exactly 0.
template <int DIR>
__device__ __forceinline__ void gather_blur(
    const float* __restrict__ S, int t, int z, int y, int x,
    float2& bc, float b0[8], float b1[8])
{
    if (DIR == 0) {
        bc = *reinterpret_cast<const float2*>(S + t);
#pragma unroll
        for (int k = 0; k < 8; ++k) {
            const int dr = c_dr[k], dc = c_dc[k];
            const bool ok = ((unsigned)(x + dr) < DX) & ((unsigned)(y + dc) < DY);
            const int delta = dr * (DY * DZ) + dc * DZ;
            const float2 bb = *reinterpret_cast<const float2*>(S + (ok ? t + delta : t));
            b0[k] = bb.x; b1[k] = bb.y;
        }
    } else {
        // Rows -1,0,+1 along x (DIR1) or y (DIR2); z-shifts built in registers.
        float2 q[3]; float em[3], ep[3];
#pragma unroll
        for (int r = 0; r < 3; ++r) {
            const int d   = r - 1;
            const int row = (DIR == 1) ? d * (DY * DZ) : d * DZ;
            const bool rok = (DIR == 1) ? ((unsigned)(x + d) < DX)
                                        : ((unsigned)(y + d) < DY);
            const float* base = S + (rok ? t + row : t);
            q[r]  = *reinterpret_cast<const float2*>(base);
            em[r] = __ldg(base - (z > 0  ? 1 : 0));   // z-1  (clamped at z==0)
            ep[r] = __ldg(base + (z < 30 ? 2 : 0));   // z+2  (clamped at z==30)
        }
        bc = q[1];
#pragma unroll
        for (int k = 0; k < 8; ++k) {
            const int r = c_dr[k] + 1, dc = c_dc[k];
            if (dc == 0)      { b0[k] = q[r].x; b1[k] = q[r].y; }
            else if (dc == 1) { b0[k] = q[r].y; b1[k] = ep[r];  }
            else              { b0[k] = em[r];  b1[k] = q[r].x; }
        }
    }
}

__device__ __forceinline__ float apply8(const uint4 w, const float* b, float bcv) {
    float wf[8];
    decode8(w, wf);
    float acc = 0.f, gs = 0.f;
#pragma unroll
    for (int k = 0; k < 8; ++k) { acc = fmaf(wf[k], b[k], acc); gs += wf[k]; }
    return fmaf(fmaf(-gs, bcv, acc), 1.f / 32767.f, bcv);
}

// ---------------------------------------------------------------------------
// Fused (iteration 1): read guidance (.cs), normalize+quantize weights,
// store the slab for iterations 2-3, AND apply the weights (still in
// registers) to blur. Saves a full 32 MB slab re-read per direction.
// ---------------------------------------------------------------------------
template <int DIR>
__global__ __launch_bounds__(256) void fused_mw_prop(
    const float* __restrict__ G, uint4* __restrict__ W,
    const float* __restrict__ S, float* __restrict__ D)
{
    const int t = (blockIdx.x * 256 + threadIdx.x) * 2;
    const int z0 = t & 31, y = (t >> 5) & 255, x = t >> 13;

    uint4 wp[2];
#pragma unroll
    for (int v = 0; v < 2; ++v) {
        const int z = z0 + v;
        float g[8];
        float asum = 0.f;
#pragma unroll
        for (int k = 0; k < 8; ++k) {
            const int dr = c_dr[k], dc = c_dc[k];
            int nx, ny, nz; bool ok;
            if (DIR == 0)      { nx = x + dr; ny = y + dc; nz = z;
                                 ok = ((unsigned)nx < DX) & ((unsigned)ny < DY); }
            else if (DIR == 1) { nx = x + dr; ny = y;      nz = z + dc;
                                 ok = ((unsigned)nx < DX) & ((unsigned)nz < DZ); }
            else               { nx = x;      ny = y + dr; nz = z + dc;
                                 ok = ((unsigned)ny < DY) & ((unsigned)nz < DZ); }
            float gv = 0.f;
            if (ok) gv = ldcs(&G[(DIR * 8 + k) * VOL + (nx * DY + ny) * DZ + nz]);
            g[k] = gv;
            asum += fabsf(gv);
        }
        const float s = 32767.f / asum;
        int q[8];
#pragma unroll
        for (int k = 0; k < 8; ++k) q[k] = __float2int_rn(g[k] * s);
        wp[v].x = (q[0] & 0xffff) | (q[1] << 16);
        wp[v].y = (q[2] & 0xffff) | (q[3] << 16);
        wp[v].z = (q[4] & 0xffff) | (q[5] << 16);
        wp[v].w = (q[6] & 0xffff) | (q[7] << 16);
    }
    stg256_sticky(&W[t], wp[0], wp[1]);

    // Apply weights (in registers) to blur immediately.
    float2 bc; float b0[8], b1[8];
    gather_blur<DIR>(S, t, z0, y, x, bc, b0, b1);
    float2 r2;
    r2.x = apply8(wp[0], b0, bc.x);
    r2.y = apply8(wp[1], b1, bc.y);
    *reinterpret_cast<float2*>(D + t) = r2;
}

// ---------------------------------------------------------------------------
// Standalone prop (iterations 2-3): 1 x LDG.256 weights + blur gather.
// ---------------------------------------------------------------------------
template <int DIR>
__global__ __launch_bounds__(256) void prop_step(
    const uint4* __restrict__ W,
    const float* __restrict__ S,
    float* __restrict__ D)
{
    const int t = (blockIdx.x * 256 + threadIdx.x) * 2;
    const int z = t & 31, y = (t >> 5) & 255, x = t >> 13;

    uint4 w0, w1;
    ldg256_sticky(&W[t], w0, w1);

    float2 bc; float b0[8], b1[8];
    gather_blur<DIR>(S, t, z, y, x, bc, b0, b1);

    float2 r2;
    r2.x = apply8(w0, b0, bc.x);
    r2.y = apply8(w1, b1, bc.y);
    *reinterpret_cast<float2*>(D + t) = r2;
}

extern "C" void kernel_launch(void* const* d_in, const int* in_sizes, int n_in,
                              void* d_out, int out_size)
{
    const float* G    = (const float*)d_in[0];  // guidance [24,256,256,32]
    const float* blur = (const float*)d_in[1];  // blur [1,256,256,32]
    float* out = (float*)d_out;

    void* wp = nullptr;  cudaGetSymbolAddress(&wp, g_weights);
    void* sp = nullptr;  cudaGetSymbolAddress(&sp, g_scratch);
    uint4* W   = (uint4*)wp;
    float* scr = (float*)sp;

    const int grid = (VOL / 2) / 256;   // 4096 blocks, 2 voxels/thread

    // Iteration 1 fused with weight construction (writes #1..#3):
    fused_mw_prop<0><<<grid, 256>>>(G, W + 0 * VOL, blur, out);   // -> out
    fused_mw_prop<1><<<grid, 256>>>(G, W + 1 * VOL, out,  scr);   // -> scr
    fused_mw_prop<2><<<grid, 256>>>(G, W + 2 * VOL, scr,  out);   // -> out

    // Iterations 2-3 (writes #4..#9; last lands in d_out):
    prop_step<0><<<grid, 256>>>(W + 0 * VOL, out, scr);
    prop_step<1><<<grid, 256>>>(W + 1 * VOL, scr, out);
    prop_step<2><<<grid, 256>>>(W + 2 * VOL, out, scr);
    prop_step<0><<<grid, 256>>>(W + 0 * VOL, scr, out);
    prop_step<1><<<grid, 256>>>(W + 1 * VOL, out, scr);
    prop_step<2><<<grid, 256>>>(W + 2 * VOL, scr, out);   // final -> d_out
}